// round 15
// baseline (speedup 1.0000x reference)
#include <cuda_runtime.h>
#include <cuda_fp16.h>
#include <cstdint>

#define NB 4096
#define ND 1024
#define NF 512
#define NEG_INF (-1e30f)
#define SCL 2048.0f
#define INV_SCL (1.0f / 2048.0f)
#define MAXG 128                 // max 32-col groups (NB/32)

typedef __half hf;

// ---------------- scratch (device globals; no allocations allowed) ----------
__device__ float g_proj[3][NB * NF];          // fp32 projections (filled in place)
__device__ float g_norm[3][NB];
__device__ float g_rnorm[3][NB];              // 1/norm
__device__ float g_normp[3][NB * 16];         // per-row norm partials (proj epilogue)
__device__ float g_outp[NB * 16];             // per-row out partials (h epilogue)
__device__ int   g_rows[3][NB];               // missing rows (compacted)
__device__ int   g_avail[3][NB];              // available rows (compacted)
__device__ int   g_cnt[3];
__device__ int   g_acnt[3];
__device__ float g_cv[3][(size_t)NB * MAXG * 3];  // per-(row,group) top-3 scores
__device__ int   g_ci[3][(size_t)NB * MAXG * 3];  // per-(row,group) top-3 real cols

__device__ hf g_xh[3][NB * ND], g_xl[3][NB * ND];   // fp16 scaled splits of inputs
__device__ hf g_wh[3][ND * NF], g_wl[3][ND * NF];   // proj weights (hi + lo)
__device__ hf g_w1h[3 * NF * NF];                   // W1 hi only
__device__ hf g_ph[3][NB * NF];                     // projections hi only

// ---------------- PTX helpers ------------------------------------------------
__device__ __forceinline__ uint32_t s2u(const void* p) {
    return (uint32_t)__cvta_generic_to_shared(p);
}
__device__ __forceinline__ void cpa(uint32_t dst, const void* src) {
    asm volatile("cp.async.cg.shared.global [%0], [%1], 16;\n" :: "r"(dst), "l"(src));
}
__device__ __forceinline__ void cpcommit() { asm volatile("cp.async.commit_group;\n"); }
__device__ __forceinline__ void cpwait1()  { asm volatile("cp.async.wait_group 1;\n"); }
__device__ __forceinline__ void cpwait0()  { asm volatile("cp.async.wait_group 0;\n"); }
__device__ __forceinline__ void ldsm4(uint32_t* r, uint32_t a) {
    asm volatile("ldmatrix.sync.aligned.m8n8.x4.shared.b16 {%0,%1,%2,%3}, [%4];\n"
                 : "=r"(r[0]), "=r"(r[1]), "=r"(r[2]), "=r"(r[3]) : "r"(a));
}
__device__ __forceinline__ void ldsm4t(uint32_t* r, uint32_t a) {
    asm volatile("ldmatrix.sync.aligned.m8n8.x4.trans.shared.b16 {%0,%1,%2,%3}, [%4];\n"
                 : "=r"(r[0]), "=r"(r[1]), "=r"(r[2]), "=r"(r[3]) : "r"(a));
}
__device__ __forceinline__ void mma_f16(float* c, const uint32_t* a, const uint32_t* b) {
    asm volatile("mma.sync.aligned.m16n8k16.row.col.f32.f16.f16.f32 "
                 "{%0,%1,%2,%3},{%4,%5,%6,%7},{%8,%9},{%0,%1,%2,%3};\n"
                 : "+f"(c[0]), "+f"(c[1]), "+f"(c[2]), "+f"(c[3])
                 : "r"(a[0]), "r"(a[1]), "r"(a[2]), "r"(a[3]), "r"(b[0]), "r"(b[1]));
}
__device__ __forceinline__ uint32_t swz(uint32_t row, uint32_t chunk) {
    return row * 128u + ((chunk ^ (row & 7u)) * 16u);
}

// ---------------- top-3 ordered insert ----------------------------------------
__device__ __forceinline__ bool better(float v, int i, float V, int I) {
    return v > V || (v == V && i < I);  // jax top_k tie-break: lower index wins
}
__device__ __forceinline__ void ins3(float v, int i, float* tv, int* ti) {
    if (!better(v, i, tv[2], ti[2])) return;
    if (better(v, i, tv[1], ti[1])) {
        tv[2] = tv[1]; ti[2] = ti[1];
        if (better(v, i, tv[0], ti[0])) {
            tv[1] = tv[0]; ti[1] = ti[0]; tv[0] = v; ti[0] = i;
        } else { tv[1] = v; ti[1] = i; }
    } else { tv[2] = v; ti[2] = i; }
}

// proj fused-stage smem layout (per stage): AH 16KB | AL 16KB | BH 8KB | BL 8KB
#define OFF_AL 16384
#define OFF_BH 32768
#define OFF_BL 40960
#define STG    49152
#define DSM    (2 * STG)

// h hi-only stage layout (per stage): AH 16KB | BH 8KB
#define HOFF_B 16384
#define STGH   24576
#define DSMH   (2 * STGH)

// hi-only sim stage layout: AH 16KB | BH 8KB
#define SOFF_B 16384
#define SSTG   24576
#define SDSM   (2 * SSTG)

// one BK=64 stage: acc1 += Ah*Bh ; acc2 += Al*Bh + Ah*Bl
__device__ __forceinline__ void stage3_nn(uint32_t base, int wm, int wn, int lane,
                                          float (&acc1)[2][4][4], float (&acc2)[2][4][4]) {
#pragma unroll
    for (int ks = 0; ks < 4; ks++) {
        uint32_t ah[2][4], al[2][4];
#pragma unroll
        for (int mt = 0; mt < 2; mt++) {
            uint32_t m_l = wm * 32 + mt * 16 + (lane & 15);
            uint32_t c = ks * 2 + (lane >> 4);
            ldsm4(ah[mt], base + swz(m_l, c));
            ldsm4(al[mt], base + OFF_AL + swz(m_l, c));
        }
        uint32_t bh[4][2], bl[4][2];
#pragma unroll
        for (int j = 0; j < 2; j++) {
            uint32_t k_l = ks * 16 + (lane & 15);
            uint32_t c = wn * 4 + j * 2 + (lane >> 4);
            uint32_t r[4];
            ldsm4t(r, base + OFF_BH + swz(k_l, c));
            bh[j * 2][0] = r[0]; bh[j * 2][1] = r[1];
            bh[j * 2 + 1][0] = r[2]; bh[j * 2 + 1][1] = r[3];
            ldsm4t(r, base + OFF_BL + swz(k_l, c));
            bl[j * 2][0] = r[0]; bl[j * 2][1] = r[1];
            bl[j * 2 + 1][0] = r[2]; bl[j * 2 + 1][1] = r[3];
        }
#pragma unroll
        for (int mt = 0; mt < 2; mt++)
#pragma unroll
            for (int nt = 0; nt < 4; nt++) {
                mma_f16(acc1[mt][nt], ah[mt], bh[nt]);
                mma_f16(acc2[mt][nt], al[mt], bh[nt]);
                mma_f16(acc2[mt][nt], ah[mt], bl[nt]);
            }
    }
}

// hi-only NN stage for h: acc += Ah*Bh
__device__ __forceinline__ void stage1_nn(uint32_t base, int wm, int wn, int lane,
                                          float (&acc)[2][4][4]) {
#pragma unroll
    for (int ks = 0; ks < 4; ks++) {
        uint32_t ah[2][4];
#pragma unroll
        for (int mt = 0; mt < 2; mt++) {
            uint32_t m_l = wm * 32 + mt * 16 + (lane & 15);
            ldsm4(ah[mt], base + swz(m_l, ks * 2 + (lane >> 4)));
        }
        uint32_t bh[4][2];
#pragma unroll
        for (int j = 0; j < 2; j++) {
            uint32_t k_l = ks * 16 + (lane & 15);
            uint32_t c = wn * 4 + j * 2 + (lane >> 4);
            uint32_t r[4];
            ldsm4t(r, base + HOFF_B + swz(k_l, c));
            bh[j * 2][0] = r[0]; bh[j * 2][1] = r[1];
            bh[j * 2 + 1][0] = r[2]; bh[j * 2 + 1][1] = r[3];
        }
#pragma unroll
        for (int mt = 0; mt < 2; mt++)
#pragma unroll
            for (int nt = 0; nt < 4; nt++) mma_f16(acc[mt][nt], ah[mt], bh[nt]);
    }
}

// hi-only NT stage: acc += Ah*Bh
__device__ __forceinline__ void stage1_nt(uint32_t base, int wm, int wn, int lane,
                                          float (&acc)[2][4][4]) {
#pragma unroll
    for (int ks = 0; ks < 4; ks++) {
        uint32_t ah[2][4];
#pragma unroll
        for (int mt = 0; mt < 2; mt++) {
            uint32_t m_l = wm * 32 + mt * 16 + (lane & 15);
            ldsm4(ah[mt], base + swz(m_l, ks * 2 + (lane >> 4)));
        }
        uint32_t bh[4][2];
#pragma unroll
        for (int j = 0; j < 2; j++) {
            uint32_t n_l = wn * 32 + j * 16 + (lane & 7) + ((lane >> 4) << 3);
            uint32_t r[4];
            ldsm4(r, base + SOFF_B + swz(n_l, ks * 2 + ((lane >> 3) & 1)));
            bh[j * 2][0] = r[0]; bh[j * 2][1] = r[1];
            bh[j * 2 + 1][0] = r[2]; bh[j * 2 + 1][1] = r[3];
        }
#pragma unroll
        for (int mt = 0; mt < 2; mt++)
#pragma unroll
            for (int nt = 0; nt < 4; nt++) mma_f16(acc[mt][nt], ah[mt], bh[nt]);
    }
}

// ---------------- tiny setup kernels -----------------------------------------
__global__ void k_reset() {
    if (threadIdx.x < 3) { g_cnt[threadIdx.x] = 0; g_acnt[threadIdx.x] = 0; }
}

__global__ void k_build(const int* __restrict__ mi) {
    const int i = blockIdx.x * blockDim.x + threadIdx.x;
    const int lane = threadIdx.x & 31;
    const int t = (i < NB) ? mi[i] : -1;
#pragma unroll
    for (int z = 0; z < 3; z++) {
        unsigned mmask = __ballot_sync(0xffffffffu, t == z + 1);
        if (mmask) {
            int leader = __ffs(mmask) - 1;
            int base = 0;
            if (lane == leader) base = atomicAdd(&g_cnt[z], __popc(mmask));
            base = __shfl_sync(0xffffffffu, base, leader);
            if (t == z + 1)
                g_rows[z][base + __popc(mmask & ((1u << lane) - 1u))] = i;
        }
        unsigned amask = __ballot_sync(0xffffffffu, t >= 0 && t != z + 1);
        if (amask) {
            int leader = __ffs(amask) - 1;
            int base = 0;
            if (lane == leader) base = atomicAdd(&g_acnt[z], __popc(amask));
            base = __shfl_sync(0xffffffffu, base, leader);
            if (t >= 0 && t != z + 1)
                g_avail[z][base + __popc(amask & ((1u << lane) - 1u))] = i;
        }
    }
}

// fp32 -> fp16 scaled hi/lo split.  mode 0: X, mode 1: W, mode 2: W1 (hi only)
__global__ void __launch_bounds__(256) k_split(const float* __restrict__ s0,
                                               const float* __restrict__ s1,
                                               const float* __restrict__ s2,
                                               int n4, int mode) {
    const int z = blockIdx.y;
    const float* src = (z == 0) ? s0 : (z == 1) ? s1 : s2;
    hf *h, *l;
    if (mode == 0)      { h = g_xh[z]; l = g_xl[z]; }
    else if (mode == 1) { h = g_wh[z]; l = g_wl[z]; }
    else                { h = g_w1h;  l = nullptr; }
    int i = blockIdx.x * 256 + threadIdx.x;
    if (i >= n4) return;
    float4 v = ((const float4*)src)[i];
    hf h0 = __float2half_rn(v.x), h1 = __float2half_rn(v.y);
    hf h2 = __float2half_rn(v.z), h3 = __float2half_rn(v.w);
    __half2* H = (__half2*)h;
    H[2 * i]     = __halves2half2(h0, h1);
    H[2 * i + 1] = __halves2half2(h2, h3);
    if (l) {
        __half2* L = (__half2*)l;
        L[2 * i]     = __halves2half2(__float2half_rn((v.x - __half2float(h0)) * SCL),
                                      __float2half_rn((v.y - __half2float(h1)) * SCL));
        L[2 * i + 1] = __halves2half2(__float2half_rn((v.z - __half2float(h2)) * SCL),
                                      __float2half_rn((v.w - __half2float(h3)) * SCL));
    }
}

// ---------------- projection GEMM + fused norm partials ----------------------
__global__ void __launch_bounds__(256) k_proj_mma(const float* __restrict__ bl,
                                                  const float* __restrict__ bv,
                                                  const float* __restrict__ ba) {
    const int z = blockIdx.z;
    const hf* Ah = g_xh[z]; const hf* Al = g_xl[z];
    const hf* Bh = g_wh[z]; const hf* Bl = g_wl[z];
    const float* bias = (z == 0) ? bl : (z == 1) ? bv : ba;
    const int m0 = blockIdx.y * 128, n0 = blockIdx.x * 64;

    extern __shared__ __align__(16) char sm[];
    const uint32_t sb = s2u(sm);
    const int tid = threadIdx.x, lane = tid & 31, warp = tid >> 5;
    const int wm = warp & 3, wn = warp >> 2;

    auto load = [&](int it, int st) {
        const int kk = it << 6;
        uint32_t b = sb + st * STG;
#pragma unroll
        for (int i = 0; i < 4; i++) {
            int c = tid + i * 256, m = c >> 3, k8 = c & 7;
            size_t off = (size_t)(m0 + m) * ND + kk + k8 * 8;
            uint32_t d = swz(m, k8);
            cpa(b + d, Ah + off);
            cpa(b + OFF_AL + d, Al + off);
        }
#pragma unroll
        for (int i = 0; i < 2; i++) {
            int c = tid + i * 256, k = c >> 3, n8 = c & 7;
            size_t off = (size_t)(kk + k) * NF + n0 + n8 * 8;
            uint32_t d = swz(k, n8);
            cpa(b + OFF_BH + d, Bh + off);
            cpa(b + OFF_BL + d, Bl + off);
        }
        cpcommit();
    };

    float acc1[2][4][4] = {}, acc2[2][4][4] = {};
    load(0, 0);
    const int ITERS = ND / 64;  // 16
    for (int it = 0; it < ITERS; it++) {
        if (it + 1 < ITERS) { load(it + 1, (it + 1) & 1); cpwait1(); } else cpwait0();
        __syncthreads();
        stage3_nn(sb + (it & 1) * STG, wm, wn, lane, acc1, acc2);
        __syncthreads();
    }

    float* C = g_proj[z]; hf* Ph = g_ph[z];
    const int g = lane >> 2, tg = lane & 3;
    float np[2][2] = {};
#pragma unroll
    for (int mt = 0; mt < 2; mt++)
#pragma unroll
        for (int nt = 0; nt < 4; nt++) {
            int col = n0 + wn * 32 + nt * 8 + tg * 2;
            float bz0 = bias[col], bz1 = bias[col + 1];
#pragma unroll
            for (int hh = 0; hh < 2; hh++) {
                int row = m0 + wm * 32 + mt * 16 + g + hh * 8;
                float v0 = acc1[mt][nt][hh * 2 + 0] + acc2[mt][nt][hh * 2 + 0] * INV_SCL + bz0;
                float v1 = acc1[mt][nt][hh * 2 + 1] + acc2[mt][nt][hh * 2 + 1] * INV_SCL + bz1;
                size_t off = (size_t)row * NF + col;
                *(float2*)(C + off) = make_float2(v0, v1);
                *(__half2*)(Ph + off) = __halves2half2(__float2half_rn(v0), __float2half_rn(v1));
                np[mt][hh] += v0 * v0 + v1 * v1;
            }
        }
#pragma unroll
    for (int mt = 0; mt < 2; mt++)
#pragma unroll
        for (int hh = 0; hh < 2; hh++) {
            float s = np[mt][hh];
            s += __shfl_xor_sync(0xffffffffu, s, 1);
            s += __shfl_xor_sync(0xffffffffu, s, 2);
            if (tg == 0) {
                int row = m0 + wm * 32 + mt * 16 + g + hh * 8;
                g_normp[z][(size_t)row * 16 + blockIdx.x * 2 + wn] = s;
            }
        }
}

// ---------------- finalize norms ----------------------------------------------
__global__ void __launch_bounds__(256) k_norm2() {
    const int z = blockIdx.y;
    const int row = blockIdx.x * 256 + threadIdx.x;
    if (row >= NB) return;
    const float* p = g_normp[z] + (size_t)row * 16;
    float s = 0.f;
#pragma unroll
    for (int j = 0; j < 16; j++) s += p[j];
    float nrm = sqrtf(s);
    g_norm[z][row] = nrm;
    g_rnorm[z][row] = 1.0f / nrm;
}

// ---------------- sim GEMM + fused per-group top-3 candidate extraction ------
__global__ void __launch_bounds__(256) k_sim_mma() {
    const int z = blockIdx.z;
    const int cnt = g_cnt[z];
    const int acnt = g_acnt[z];
    const int m0 = blockIdx.y * 128;
    const int n0 = blockIdx.x * 64;
    if (m0 >= cnt || n0 >= acnt) return;
    const hf* Ph = g_ph[z];

    extern __shared__ __align__(16) char sm[];
    const uint32_t sb = s2u(sm);
    const int tid = threadIdx.x, lane = tid & 31, warp = tid >> 5;
    const int wm = warp & 3, wn = warp >> 2;

    __shared__ int rows[128];
    __shared__ int cols[64];
    __shared__ float rncs[64];
    if (tid < 128) {
        int mm = m0 + tid; if (mm >= cnt) mm = cnt - 1;
        rows[tid] = g_rows[z][mm];
    } else if (tid < 192) {
        int nn = n0 + tid - 128; if (nn >= acnt) nn = acnt - 1;
        int real = g_avail[z][nn];
        cols[tid - 128] = real;
        rncs[tid - 128] = g_rnorm[z][real];
    }
    __syncthreads();

    auto load = [&](int it, int st) {
        const int kk = it << 6;
        uint32_t b = sb + st * SSTG;
#pragma unroll
        for (int i = 0; i < 4; i++) {
            int c = tid + i * 256, m = c >> 3, k8 = c & 7;
            cpa(b + swz(m, k8), Ph + (size_t)rows[m] * NF + kk + k8 * 8);
        }
#pragma unroll
        for (int i = 0; i < 2; i++) {
            int c = tid + i * 256, n = c >> 3, k8 = c & 7;
            cpa(b + SOFF_B + swz(n, k8), Ph + (size_t)cols[n] * NF + kk + k8 * 8);
        }
        cpcommit();
    };

    float acc[2][4][4] = {};
    load(0, 0);
    const int ITERS = NF / 64;  // 8
    for (int it = 0; it < ITERS; it++) {
        if (it + 1 < ITERS) { load(it + 1, (it + 1) & 1); cpwait1(); } else cpwait0();
        __syncthreads();
        stage1_nt(sb + (it & 1) * SSTG, wm, wn, lane, acc);
        __syncthreads();
    }

    // epilogue: per-row top-3 over this warp's 32 cols (normalized scores)
    const int g = lane >> 2, tg = lane & 3;
    const int grp = blockIdx.x * 2 + wn;
    float* CV = g_cv[z]; int* CI = g_ci[z];
#pragma unroll
    for (int mt = 0; mt < 2; mt++)
#pragma unroll
        for (int hh = 0; hh < 2; hh++) {
            float tv[3] = {NEG_INF, NEG_INF, NEG_INF};
            int   ti[3] = {NB, NB, NB};
#pragma unroll
            for (int nt = 0; nt < 4; nt++)
#pragma unroll
                for (int q = 0; q < 2; q++) {
                    int local = wn * 32 + nt * 8 + tg * 2 + q;
                    if (n0 + local < acnt)
                        ins3(acc[mt][nt][hh * 2 + q] * rncs[local], cols[local], tv, ti);
                }
            // merge across the 4 tg lanes
#pragma unroll
            for (int o = 1; o <= 2; o <<= 1) {
                float ov[3]; int oi[3];
#pragma unroll
                for (int j = 0; j < 3; j++) {
                    ov[j] = __shfl_xor_sync(0xffffffffu, tv[j], o);
                    oi[j] = __shfl_xor_sync(0xffffffffu, ti[j], o);
                }
#pragma unroll
                for (int j = 0; j < 3; j++) ins3(ov[j], oi[j], tv, ti);
            }
            int m = m0 + wm * 32 + mt * 16 + g + hh * 8;
            if (tg == 0 && m < cnt) {
                size_t base = (size_t)m * (MAXG * 3) + grp * 3;
                CV[base + 0] = tv[0]; CI[base + 0] = ti[0];
                CV[base + 1] = tv[1]; CI[base + 1] = ti[1];
                CV[base + 2] = tv[2]; CI[base + 2] = ti[2];
            }
        }
}

// ---------------- top-3: merge prefiltered candidates + exact rescoring ------
__global__ void __launch_bounds__(128) k_topk() {
    const int z = blockIdx.z;
    const int m = blockIdx.x;
    const int cnt = g_cnt[z];
    if (m >= cnt) return;
    const int acnt = g_acnt[z];
    const int r = g_rows[z][m];
    float* P = g_proj[z];
    hf* Ph = g_ph[z];
    const float* nrm = g_norm[z];
    const float ni = nrm[r];
    const int tid = threadIdx.x;

    // phase 1: per-thread top-3 over prefiltered (val,idx) entries
    const int tot = ((acnt + 31) >> 5) * 3;
    const float* cv = g_cv[z] + (size_t)m * (MAXG * 3);
    const int*   ci = g_ci[z] + (size_t)m * (MAXG * 3);
    float v0 = NEG_INF, v1 = NEG_INF, v2 = NEG_INF;
    int   i0 = NB, i1 = NB, i2 = NB;
    for (int t = tid; t < tot; t += 128) {
        float s = cv[t]; int n = ci[t];
        if (n >= NB) continue;
        if (better(s, n, v0, i0)) { v2 = v1; i2 = i1; v1 = v0; i1 = i0; v0 = s; i0 = n; }
        else if (better(s, n, v1, i1)) { v2 = v1; i2 = i1; v1 = s; i1 = n; }
        else if (better(s, n, v2, i2)) { v2 = s; i2 = n; }
    }

    __shared__ float sv[384];
    __shared__ int   si[384];
    sv[tid * 3 + 0] = v0; si[tid * 3 + 0] = i0;
    sv[tid * 3 + 1] = v1; si[tid * 3 + 1] = i1;
    sv[tid * 3 + 2] = v2; si[tid * 3 + 2] = i2;
    __syncthreads();

    // phase 2: merge union -> approx top-8 candidate set
    __shared__ int cand[8];
    if (tid == 0) {
        float bv[8]; int bx[8];
#pragma unroll
        for (int j = 0; j < 8; j++) { bv[j] = NEG_INF; bx[j] = NB; }
        for (int t = 0; t < 384; t++) {
            float s = sv[t]; int n = si[t];
            if (n >= NB) continue;
            if (better(s, n, bv[7], bx[7])) {
                int j = 7;
                while (j > 0 && better(s, n, bv[j - 1], bx[j - 1])) {
                    bv[j] = bv[j - 1]; bx[j] = bx[j - 1]; j--;
                }
                bv[j] = s; bx[j] = n;
            }
        }
#pragma unroll
        for (int j = 0; j < 8; j++) cand[j] = bx[j];
    }
    __syncthreads();

    // phase 3: exact fp32 cosine sims for the 8 candidates
    __shared__ float cval[8];
    const int warp = tid >> 5, lane = tid & 31;
    const float* pr = P + (size_t)r * NF;
    for (int c = warp; c < 8; c += 4) {
        int n = cand[c];
        if (n >= NB) { if (lane == 0) cval[c] = NEG_INF; continue; }
        const float* pc = P + (size_t)n * NF;
        float s = 0.f;
#pragma unroll 4
        for (int f = lane; f < NF; f += 32) s += pr[f] * pc[f];
#pragma unroll
        for (int o = 16; o; o >>= 1) s += __shfl_xor_sync(0xffffffffu, s, o);
        if (lane == 0) cval[c] = s / fmaxf(ni * nrm[n], 1e-8f);
    }
    __syncthreads();

    // phase 4: exact top-3 of the 8 + softmax
    __shared__ float w[3];
    __shared__ int   bi[3];
    if (tid == 0) {
        float b0 = NEG_INF, b1 = NEG_INF, b2 = NEG_INF;
        int   j0 = NB, j1 = NB, j2 = NB;
        for (int t = 0; t < 8; t++) {
            float s = cval[t]; int n = cand[t];
            if (n >= NB) continue;
            if (better(s, n, b0, j0)) { b2 = b1; j2 = j1; b1 = b0; j1 = j0; b0 = s; j0 = n; }
            else if (better(s, n, b1, j1)) { b2 = b1; j2 = j1; b1 = s; j1 = n; }
            else if (better(s, n, b2, j2)) { b2 = s; j2 = n; }
        }
        float e0 = 1.0f, e1 = expf(b1 - b0), e2 = expf(b2 - b0);
        float inv = 1.0f / (e0 + e1 + e2);
        w[0] = e0 * inv; w[1] = e1 * inv; w[2] = e2 * inv;
        bi[0] = j0; bi[1] = j1; bi[2] = j2;
    }
    __syncthreads();

    // phase 5: weighted fill + refresh fp16 hi
    const float* f0 = P + (size_t)bi[0] * NF;
    const float* f1 = P + (size_t)bi[1] * NF;
    const float* f2 = P + (size_t)bi[2] * NF;
    const float w0 = w[0], w1 = w[1], w2 = w[2];
    for (int f = tid * 2; f < NF; f += 256) {
        float a0 = w0 * f0[f]     + w1 * f1[f]     + w2 * f2[f];
        float a1 = w0 * f0[f + 1] + w1 * f1[f + 1] + w2 * f2[f + 1];
        size_t off = (size_t)r * NF + f;
        *(float2*)(P + off) = make_float2(a0, a1);
        *(__half2*)(Ph + off) = __halves2half2(__float2half_rn(a0), __float2half_rn(a1));
    }
}

// ---------------- fused concat GEMM + ReLU + W2-dot partials -----------------
__global__ void __launch_bounds__(256) k_h_mma(const float* __restrict__ b1,
                                               const float* __restrict__ W2) {
    const int m0 = blockIdx.y * 128, n0 = blockIdx.x * 64;
    extern __shared__ __align__(16) char sm[];
    const uint32_t sb = s2u(sm);
    const int tid = threadIdx.x, lane = tid & 31, warp = tid >> 5;
    const int wm = warp & 3, wn = warp >> 2;

    auto load = [&](int it, int st) {
        const int mod = it >> 3, kk = (it & 7) << 6;
        const hf* Ah = g_ph[mod];
        uint32_t b = sb + st * STGH;
#pragma unroll
        for (int i = 0; i < 4; i++) {
            int c = tid + i * 256, m = c >> 3, k8 = c & 7;
            cpa(b + swz(m, k8), Ah + (size_t)(m0 + m) * NF + kk + k8 * 8);
        }
#pragma unroll
        for (int i = 0; i < 2; i++) {
            int c = tid + i * 256, k = c >> 3, n8 = c & 7;
            size_t off = (size_t)(mod * NF + kk + k) * NF + n0 + n8 * 8;
            cpa(b + HOFF_B + swz(k, n8), g_w1h + off);
        }
        cpcommit();
    };

    float acc[2][4][4] = {};
    load(0, 0);
    const int ITERS = 24;  // 3 modalities x 8 BK-tiles
    for (int it = 0; it < ITERS; it++) {
        if (it + 1 < ITERS) { load(it + 1, (it + 1) & 1); cpwait1(); } else cpwait0();
        __syncthreads();
        stage1_nn(sb + (it & 1) * STGH, wm, wn, lane, acc);
        __syncthreads();
    }

    const int g = lane >> 2, tg = lane & 3;
    float op[2][2] = {};
#pragma unroll
    for (int mt = 0; mt < 2; mt++)
#pragma unroll
        for (int nt = 0; nt < 4; nt++) {
            int col = n0 + wn * 32 + nt * 8 + tg * 2;
            float bz0 = b1[col], bz1 = b1[col + 1];
            float w20 = W2[col], w21 = W2[col + 1];
#pragma unroll
            for (int hh = 0; hh < 2; hh++) {
                float v0 = fmaxf(acc[mt][nt][hh * 2 + 0] + bz0, 0.f);
                float v1 = fmaxf(acc[mt][nt][hh * 2 + 1] + bz1, 0.f);
                op[mt][hh] += v0 * w20 + v1 * w21;
            }
        }
#pragma unroll
    for (int mt = 0; mt < 2; mt++)
#pragma unroll
        for (int hh = 0; hh < 2; hh++) {
            float s = op[mt][hh];
            s += __shfl_xor_sync(0xffffffffu, s, 1);
            s += __shfl_xor_sync(0xffffffffu, s, 2);
            if (tg == 0) {
                int row = m0 + wm * 32 + mt * 16 + g + hh * 8;
                g_outp[(size_t)row * 16 + blockIdx.x * 2 + wn] = s;
            }
        }
}

// ---------------- out[m] = sum of 16 partials + b2 ---------------------------
__global__ void __launch_bounds__(256) k_out2(const float* __restrict__ b2,
                                              float* __restrict__ out) {
    const int m = blockIdx.x * 256 + threadIdx.x;
    if (m >= NB) return;
    const float* p = g_outp + (size_t)m * 16;
    float s = 0.f;
#pragma unroll
    for (int j = 0; j < 16; j++) s += p[j];
    out[m] = s + b2[0];
}

// ---------------- launcher ----------------------------------------------------
extern "C" void kernel_launch(void* const* d_in, const int* in_sizes, int n_in,
                              void* d_out, int out_size) {
    const float* lang = (const float*)d_in[0];
    const float* vid  = (const float*)d_in[1];
    const float* aud  = (const float*)d_in[2];
    const int*   mi   = (const int*)d_in[3];
    const float* Wl   = (const float*)d_in[4];
    const float* bl   = (const float*)d_in[5];
    const float* Wv   = (const float*)d_in[6];
    const float* bv   = (const float*)d_in[7];
    const float* Wa   = (const float*)d_in[8];
    const float* ba   = (const float*)d_in[9];
    const float* W1   = (const float*)d_in[10];
    const float* b1   = (const float*)d_in[11];
    const float* W2   = (const float*)d_in[12];
    const float* b2   = (const float*)d_in[13];
    float* out = (float*)d_out;

    cudaFuncSetAttribute(k_proj_mma, cudaFuncAttributeMaxDynamicSharedMemorySize, DSM);
    cudaFuncSetAttribute(k_sim_mma,  cudaFuncAttributeMaxDynamicSharedMemorySize, SDSM);
    cudaFuncSetAttribute(k_h_mma,    cudaFuncAttributeMaxDynamicSharedMemorySize, DSMH);

    k_reset<<<1, 32>>>();
    k_build<<<NB / 256, 256>>>(mi);

    k_split<<<dim3((NB * ND / 4) / 256, 3), 256>>>(lang, vid, aud, NB * ND / 4, 0);
    k_split<<<dim3((ND * NF / 4) / 256, 3), 256>>>(Wl, Wv, Wa, ND * NF / 4, 1);
    k_split<<<dim3((3 * NF * NF / 4) / 256, 1), 256>>>(W1, W1, W1, 3 * NF * NF / 4, 2);

    k_proj_mma<<<dim3(NF / 64, NB / 128, 3), 256, DSM>>>(bl, bv, ba);
    k_norm2<<<dim3(NB / 256, 3), 256>>>();

    k_sim_mma<<<dim3(NB / 64, NB / 128, 3), 256, SDSM>>>();
    k_topk<<<dim3(NB, 1, 3), 128>>>();

    k_h_mma<<<dim3(NF / 64, NB / 128), 256, DSMH>>>(b1, W2);
    k_out2<<<NB / 256, 256>>>(b2, out);
}

// round 17
// speedup vs baseline: 1.0293x; 1.0293x over previous
#include <cuda_runtime.h>
#include <cuda_fp16.h>
#include <cstdint>

#define NB 4096
#define ND 1024
#define NF 512
#define NEG_INF (-1e30f)
#define SCL 2048.0f
#define INV_SCL (1.0f / 2048.0f)

typedef __half hf;

// ---------------- scratch (device globals; no allocations allowed) ----------
__device__ float g_proj[3][NB * NF];          // fp32 projections (filled in place)
__device__ float g_norm[3][NB];
__device__ float g_rnorm[3][NB];              // 1/norm (phase-1 scan only)
__device__ float g_normp[3][NB * 16];         // per-row norm partials (proj epilogue)
__device__ float g_outp[NB * 16];             // per-row out partials (h epilogue)
__device__ int   g_rows[3][NB];               // missing rows (compacted)
__device__ int   g_avail[3][NB];              // available rows (compacted)
__device__ int   g_cnt[3];
__device__ int   g_acnt[3];
__device__ float g_sim[3][(size_t)NB * NB];

__device__ hf g_xh[3][NB * ND], g_xl[3][NB * ND];   // fp16 scaled splits of inputs
__device__ hf g_wh[3][ND * NF], g_wl[3][ND * NF];   // proj weights (hi + lo)
__device__ hf g_w1h[3 * NF * NF];                   // W1 hi only
__device__ hf g_ph[3][NB * NF];                     // projections hi only

// ---------------- PTX helpers ------------------------------------------------
__device__ __forceinline__ uint32_t s2u(const void* p) {
    return (uint32_t)__cvta_generic_to_shared(p);
}
__device__ __forceinline__ void cpa(uint32_t dst, const void* src) {
    asm volatile("cp.async.cg.shared.global [%0], [%1], 16;\n" :: "r"(dst), "l"(src));
}
__device__ __forceinline__ void cpcommit() { asm volatile("cp.async.commit_group;\n"); }
__device__ __forceinline__ void cpwait1()  { asm volatile("cp.async.wait_group 1;\n"); }
__device__ __forceinline__ void cpwait0()  { asm volatile("cp.async.wait_group 0;\n"); }
__device__ __forceinline__ void ldsm4(uint32_t* r, uint32_t a) {
    asm volatile("ldmatrix.sync.aligned.m8n8.x4.shared.b16 {%0,%1,%2,%3}, [%4];\n"
                 : "=r"(r[0]), "=r"(r[1]), "=r"(r[2]), "=r"(r[3]) : "r"(a));
}
__device__ __forceinline__ void ldsm4t(uint32_t* r, uint32_t a) {
    asm volatile("ldmatrix.sync.aligned.m8n8.x4.trans.shared.b16 {%0,%1,%2,%3}, [%4];\n"
                 : "=r"(r[0]), "=r"(r[1]), "=r"(r[2]), "=r"(r[3]) : "r"(a));
}
__device__ __forceinline__ void mma_f16(float* c, const uint32_t* a, const uint32_t* b) {
    asm volatile("mma.sync.aligned.m16n8k16.row.col.f32.f16.f16.f32 "
                 "{%0,%1,%2,%3},{%4,%5,%6,%7},{%8,%9},{%0,%1,%2,%3};\n"
                 : "+f"(c[0]), "+f"(c[1]), "+f"(c[2]), "+f"(c[3])
                 : "r"(a[0]), "r"(a[1]), "r"(a[2]), "r"(a[3]), "r"(b[0]), "r"(b[1]));
}
__device__ __forceinline__ uint32_t swz(uint32_t row, uint32_t chunk) {
    return row * 128u + ((chunk ^ (row & 7u)) * 16u);
}

// proj fused-stage smem layout (per stage): AH 16KB | AL 16KB | BH 8KB | BL 8KB
#define OFF_AL 16384
#define OFF_BH 32768
#define OFF_BL 40960
#define STG    49152
#define DSM    (2 * STG)

// h hi-only stage layout (per stage): AH 16KB | BH 8KB
#define HOFF_B 16384
#define STGH   24576
#define DSMH   (2 * STGH)

// hi-only sim stage layout: AH 16KB | BH 8KB
#define SOFF_B 16384
#define SSTG   24576
#define SDSM   (2 * SSTG)

// one BK=64 stage: acc1 += Ah*Bh ; acc2 += Al*Bh + Ah*Bl
__device__ __forceinline__ void stage3_nn(uint32_t base, int wm, int wn, int lane,
                                          float (&acc1)[2][4][4], float (&acc2)[2][4][4]) {
#pragma unroll
    for (int ks = 0; ks < 4; ks++) {
        uint32_t ah[2][4], al[2][4];
#pragma unroll
        for (int mt = 0; mt < 2; mt++) {
            uint32_t m_l = wm * 32 + mt * 16 + (lane & 15);
            uint32_t c = ks * 2 + (lane >> 4);
            ldsm4(ah[mt], base + swz(m_l, c));
            ldsm4(al[mt], base + OFF_AL + swz(m_l, c));
        }
        uint32_t bh[4][2], bl[4][2];
#pragma unroll
        for (int j = 0; j < 2; j++) {
            uint32_t k_l = ks * 16 + (lane & 15);
            uint32_t c = wn * 4 + j * 2 + (lane >> 4);
            uint32_t r[4];
            ldsm4t(r, base + OFF_BH + swz(k_l, c));
            bh[j * 2][0] = r[0]; bh[j * 2][1] = r[1];
            bh[j * 2 + 1][0] = r[2]; bh[j * 2 + 1][1] = r[3];
            ldsm4t(r, base + OFF_BL + swz(k_l, c));
            bl[j * 2][0] = r[0]; bl[j * 2][1] = r[1];
            bl[j * 2 + 1][0] = r[2]; bl[j * 2 + 1][1] = r[3];
        }
#pragma unroll
        for (int mt = 0; mt < 2; mt++)
#pragma unroll
            for (int nt = 0; nt < 4; nt++) {
                mma_f16(acc1[mt][nt], ah[mt], bh[nt]);
                mma_f16(acc2[mt][nt], al[mt], bh[nt]);
                mma_f16(acc2[mt][nt], ah[mt], bl[nt]);
            }
    }
}

// hi-only NN stage for h: acc += Ah*Bh
__device__ __forceinline__ void stage1_nn(uint32_t base, int wm, int wn, int lane,
                                          float (&acc)[2][4][4]) {
#pragma unroll
    for (int ks = 0; ks < 4; ks++) {
        uint32_t ah[2][4];
#pragma unroll
        for (int mt = 0; mt < 2; mt++) {
            uint32_t m_l = wm * 32 + mt * 16 + (lane & 15);
            ldsm4(ah[mt], base + swz(m_l, ks * 2 + (lane >> 4)));
        }
        uint32_t bh[4][2];
#pragma unroll
        for (int j = 0; j < 2; j++) {
            uint32_t k_l = ks * 16 + (lane & 15);
            uint32_t c = wn * 4 + j * 2 + (lane >> 4);
            uint32_t r[4];
            ldsm4t(r, base + HOFF_B + swz(k_l, c));
            bh[j * 2][0] = r[0]; bh[j * 2][1] = r[1];
            bh[j * 2 + 1][0] = r[2]; bh[j * 2 + 1][1] = r[3];
        }
#pragma unroll
        for (int mt = 0; mt < 2; mt++)
#pragma unroll
            for (int nt = 0; nt < 4; nt++) mma_f16(acc[mt][nt], ah[mt], bh[nt]);
    }
}

// hi-only NT stage: acc += Ah*Bh
__device__ __forceinline__ void stage1_nt(uint32_t base, int wm, int wn, int lane,
                                          float (&acc)[2][4][4]) {
#pragma unroll
    for (int ks = 0; ks < 4; ks++) {
        uint32_t ah[2][4];
#pragma unroll
        for (int mt = 0; mt < 2; mt++) {
            uint32_t m_l = wm * 32 + mt * 16 + (lane & 15);
            ldsm4(ah[mt], base + swz(m_l, ks * 2 + (lane >> 4)));
        }
        uint32_t bh[4][2];
#pragma unroll
        for (int j = 0; j < 2; j++) {
            uint32_t n_l = wn * 32 + j * 16 + (lane & 7) + ((lane >> 4) << 3);
            uint32_t r[4];
            ldsm4(r, base + SOFF_B + swz(n_l, ks * 2 + ((lane >> 3) & 1)));
            bh[j * 2][0] = r[0]; bh[j * 2][1] = r[1];
            bh[j * 2 + 1][0] = r[2]; bh[j * 2 + 1][1] = r[3];
        }
#pragma unroll
        for (int mt = 0; mt < 2; mt++)
#pragma unroll
            for (int nt = 0; nt < 4; nt++) mma_f16(acc[mt][nt], ah[mt], bh[nt]);
    }
}

// ---------------- combined split kernel (all 7 tensors) + counter reset -------
// seg: 0-2 = X[z] (hi+lo), 3-5 = W[z] (hi+lo), 6 = W1 (hi only)
__global__ void __launch_bounds__(256) k_splitall(
    const float* __restrict__ x0, const float* __restrict__ x1, const float* __restrict__ x2,
    const float* __restrict__ w0, const float* __restrict__ w1, const float* __restrict__ w2,
    const float* __restrict__ w1c) {
    const int seg = blockIdx.y;
    if (seg == 0 && blockIdx.x == 0 && threadIdx.x < 3) {
        g_cnt[threadIdx.x] = 0; g_acnt[threadIdx.x] = 0;
    }
    const float* src;
    hf *h, *l;
    int n4;
    switch (seg) {
        case 0: src = x0; h = g_xh[0]; l = g_xl[0]; n4 = NB * ND / 4; break;
        case 1: src = x1; h = g_xh[1]; l = g_xl[1]; n4 = NB * ND / 4; break;
        case 2: src = x2; h = g_xh[2]; l = g_xl[2]; n4 = NB * ND / 4; break;
        case 3: src = w0; h = g_wh[0]; l = g_wl[0]; n4 = ND * NF / 4; break;
        case 4: src = w1; h = g_wh[1]; l = g_wl[1]; n4 = ND * NF / 4; break;
        case 5: src = w2; h = g_wh[2]; l = g_wl[2]; n4 = ND * NF / 4; break;
        default: src = w1c; h = g_w1h; l = nullptr; n4 = 3 * NF * NF / 4; break;
    }
    int i = blockIdx.x * 256 + threadIdx.x;
    if (i >= n4) return;
    float4 v = ((const float4*)src)[i];
    hf h0 = __float2half_rn(v.x), h1 = __float2half_rn(v.y);
    hf h2 = __float2half_rn(v.z), h3 = __float2half_rn(v.w);
    __half2* H = (__half2*)h;
    H[2 * i]     = __halves2half2(h0, h1);
    H[2 * i + 1] = __halves2half2(h2, h3);
    if (l) {
        __half2* L = (__half2*)l;
        L[2 * i]     = __halves2half2(__float2half_rn((v.x - __half2float(h0)) * SCL),
                                      __float2half_rn((v.y - __half2float(h1)) * SCL));
        L[2 * i + 1] = __halves2half2(__float2half_rn((v.z - __half2float(h2)) * SCL),
                                      __float2half_rn((v.w - __half2float(h3)) * SCL));
    }
}

// build missing + available lists (warp-aggregated atomics)
__global__ void k_build(const int* __restrict__ mi) {
    const int i = blockIdx.x * blockDim.x + threadIdx.x;
    const int lane = threadIdx.x & 31;
    const int t = (i < NB) ? mi[i] : -1;
#pragma unroll
    for (int z = 0; z < 3; z++) {
        unsigned mmask = __ballot_sync(0xffffffffu, t == z + 1);
        if (mmask) {
            int leader = __ffs(mmask) - 1;
            int base = 0;
            if (lane == leader) base = atomicAdd(&g_cnt[z], __popc(mmask));
            base = __shfl_sync(0xffffffffu, base, leader);
            if (t == z + 1)
                g_rows[z][base + __popc(mmask & ((1u << lane) - 1u))] = i;
        }
        unsigned amask = __ballot_sync(0xffffffffu, t >= 0 && t != z + 1);
        if (amask) {
            int leader = __ffs(amask) - 1;
            int base = 0;
            if (lane == leader) base = atomicAdd(&g_acnt[z], __popc(amask));
            base = __shfl_sync(0xffffffffu, base, leader);
            if (t >= 0 && t != z + 1)
                g_avail[z][base + __popc(amask & ((1u << lane) - 1u))] = i;
        }
    }
}

// ---------------- projection GEMM + fused norm partials ----------------------
__global__ void __launch_bounds__(256) k_proj_mma(const float* __restrict__ bl,
                                                  const float* __restrict__ bv,
                                                  const float* __restrict__ ba) {
    const int z = blockIdx.z;
    const hf* Ah = g_xh[z]; const hf* Al = g_xl[z];
    const hf* Bh = g_wh[z]; const hf* Bl = g_wl[z];
    const float* bias = (z == 0) ? bl : (z == 1) ? bv : ba;
    const int m0 = blockIdx.y * 128, n0 = blockIdx.x * 64;

    extern __shared__ __align__(16) char sm[];
    const uint32_t sb = s2u(sm);
    const int tid = threadIdx.x, lane = tid & 31, warp = tid >> 5;
    const int wm = warp & 3, wn = warp >> 2;

    auto load = [&](int it, int st) {
        const int kk = it << 6;
        uint32_t b = sb + st * STG;
#pragma unroll
        for (int i = 0; i < 4; i++) {
            int c = tid + i * 256, m = c >> 3, k8 = c & 7;
            size_t off = (size_t)(m0 + m) * ND + kk + k8 * 8;
            uint32_t d = swz(m, k8);
            cpa(b + d, Ah + off);
            cpa(b + OFF_AL + d, Al + off);
        }
#pragma unroll
        for (int i = 0; i < 2; i++) {
            int c = tid + i * 256, k = c >> 3, n8 = c & 7;
            size_t off = (size_t)(kk + k) * NF + n0 + n8 * 8;
            uint32_t d = swz(k, n8);
            cpa(b + OFF_BH + d, Bh + off);
            cpa(b + OFF_BL + d, Bl + off);
        }
        cpcommit();
    };

    float acc1[2][4][4] = {}, acc2[2][4][4] = {};
    load(0, 0);
    const int ITERS = ND / 64;  // 16
    for (int it = 0; it < ITERS; it++) {
        if (it + 1 < ITERS) { load(it + 1, (it + 1) & 1); cpwait1(); } else cpwait0();
        __syncthreads();
        stage3_nn(sb + (it & 1) * STG, wm, wn, lane, acc1, acc2);
        __syncthreads();
    }

    float* C = g_proj[z]; hf* Ph = g_ph[z];
    const int g = lane >> 2, tg = lane & 3;
    float np[2][2] = {};
#pragma unroll
    for (int mt = 0; mt < 2; mt++)
#pragma unroll
        for (int nt = 0; nt < 4; nt++) {
            int col = n0 + wn * 32 + nt * 8 + tg * 2;
            float bz0 = bias[col], bz1 = bias[col + 1];
#pragma unroll
            for (int hh = 0; hh < 2; hh++) {
                int row = m0 + wm * 32 + mt * 16 + g + hh * 8;
                float v0 = acc1[mt][nt][hh * 2 + 0] + acc2[mt][nt][hh * 2 + 0] * INV_SCL + bz0;
                float v1 = acc1[mt][nt][hh * 2 + 1] + acc2[mt][nt][hh * 2 + 1] * INV_SCL + bz1;
                size_t off = (size_t)row * NF + col;
                *(float2*)(C + off) = make_float2(v0, v1);
                *(__half2*)(Ph + off) = __halves2half2(__float2half_rn(v0), __float2half_rn(v1));
                np[mt][hh] += v0 * v0 + v1 * v1;
            }
        }
#pragma unroll
    for (int mt = 0; mt < 2; mt++)
#pragma unroll
        for (int hh = 0; hh < 2; hh++) {
            float s = np[mt][hh];
            s += __shfl_xor_sync(0xffffffffu, s, 1);
            s += __shfl_xor_sync(0xffffffffu, s, 2);
            if (tg == 0) {
                int row = m0 + wm * 32 + mt * 16 + g + hh * 8;
                g_normp[z][(size_t)row * 16 + blockIdx.x * 2 + wn] = s;
            }
        }
}

// ---------------- finalize norms ----------------------------------------------
__global__ void __launch_bounds__(256) k_norm2() {
    const int z = blockIdx.y;
    const int row = blockIdx.x * 256 + threadIdx.x;
    if (row >= NB) return;
    const float* p = g_normp[z] + (size_t)row * 16;
    float s = 0.f;
#pragma unroll
    for (int j = 0; j < 16; j++) s += p[j];
    float nrm = sqrtf(s);
    g_norm[z][row] = nrm;
    g_rnorm[z][row] = 1.0f / nrm;
}

// ---------------- sim GEMM (hi-only NT, gathered rows AND cols) --------------
__global__ void __launch_bounds__(256) k_sim_mma() {
    const int z = blockIdx.z;
    const int cnt = g_cnt[z];
    const int acnt = g_acnt[z];
    const int m0 = blockIdx.y * 128;
    const int n0 = blockIdx.x * 64;
    if (m0 >= cnt || n0 >= acnt) return;
    const hf* Ph = g_ph[z];

    extern __shared__ __align__(16) char sm[];
    const uint32_t sb = s2u(sm);
    const int tid = threadIdx.x, lane = tid & 31, warp = tid >> 5;
    const int wm = warp & 3, wn = warp >> 2;

    __shared__ int rows[128];
    __shared__ int cols[64];
    if (tid < 128) {
        int mm = m0 + tid; if (mm >= cnt) mm = cnt - 1;
        rows[tid] = g_rows[z][mm];
    } else if (tid < 192) {
        int nn = n0 + tid - 128; if (nn >= acnt) nn = acnt - 1;
        cols[tid - 128] = g_avail[z][nn];
    }
    __syncthreads();

    auto load = [&](int it, int st) {
        const int kk = it << 6;
        uint32_t b = sb + st * SSTG;
#pragma unroll
        for (int i = 0; i < 4; i++) {
            int c = tid + i * 256, m = c >> 3, k8 = c & 7;
            cpa(b + swz(m, k8), Ph + (size_t)rows[m] * NF + kk + k8 * 8);
        }
#pragma unroll
        for (int i = 0; i < 2; i++) {
            int c = tid + i * 256, n = c >> 3, k8 = c & 7;
            cpa(b + SOFF_B + swz(n, k8), Ph + (size_t)cols[n] * NF + kk + k8 * 8);
        }
        cpcommit();
    };

    float acc[2][4][4] = {};
    load(0, 0);
    const int ITERS = NF / 64;  // 8
    for (int it = 0; it < ITERS; it++) {
        if (it + 1 < ITERS) { load(it + 1, (it + 1) & 1); cpwait1(); } else cpwait0();
        __syncthreads();
        stage1_nt(sb + (it & 1) * SSTG, wm, wn, lane, acc);
        __syncthreads();
    }

    float* S = g_sim[z];
    int g = lane >> 2, tg = lane & 3;
#pragma unroll
    for (int mt = 0; mt < 2; mt++)
#pragma unroll
        for (int nt = 0; nt < 4; nt++) {
            int col = n0 + wn * 32 + nt * 8 + tg * 2;
#pragma unroll
            for (int hh = 0; hh < 2; hh++) {
                int m = m0 + wm * 32 + mt * 16 + g + hh * 8;
                if (m < cnt)
                    *(float2*)(S + (size_t)m * NB + col) =
                        make_float2(acc[mt][nt][hh * 2 + 0], acc[mt][nt][hh * 2 + 1]);
            }
        }
}

// ---------------- top-3 via approx top-8 + exact fp32 rescoring ---------------
__device__ __forceinline__ bool better(float v, int i, float V, int I) {
    return v > V || (v == V && i < I);  // jax top_k tie-break: lower index wins
}

__global__ void __launch_bounds__(128) k_topk() {
    const int z = blockIdx.z;
    const int m = blockIdx.x;
    const int cnt = g_cnt[z];
    if (m >= cnt) return;
    const int acnt = g_acnt[z];
    const int r = g_rows[z][m];
    const int* avail = g_avail[z];
    float* P = g_proj[z];
    hf* Ph = g_ph[z];
    const float* nrm = g_norm[z];
    const float* rn = g_rnorm[z];
    const float ni = nrm[r];
    const float* srow = g_sim[z] + (size_t)m * NB;
    const int tid = threadIdx.x;

    // phase 1: approx top-3 scan (ranking invariant under positive 1/ni factor)
    float v0 = NEG_INF, v1 = NEG_INF, v2 = NEG_INF;
    int   i0 = NB, i1 = NB, i2 = NB;
    for (int n = tid; n < acnt; n += 128) {
        int real = avail[n];
        float s = srow[n] * rn[real];
        if (better(s, real, v0, i0)) { v2 = v1; i2 = i1; v1 = v0; i1 = i0; v0 = s; i0 = real; }
        else if (better(s, real, v1, i1)) { v2 = v1; i2 = i1; v1 = s; i1 = real; }
        else if (better(s, real, v2, i2)) { v2 = s; i2 = real; }
    }

    __shared__ float sv[384];
    __shared__ int   si[384];
    sv[tid * 3 + 0] = v0; si[tid * 3 + 0] = i0;
    sv[tid * 3 + 1] = v1; si[tid * 3 + 1] = i1;
    sv[tid * 3 + 2] = v2; si[tid * 3 + 2] = i2;
    __syncthreads();

    // phase 2: merge union -> approx top-8 candidate set
    __shared__ int cand[8];
    if (tid == 0) {
        float bv[8]; int bx[8];
#pragma unroll
        for (int j = 0; j < 8; j++) { bv[j] = NEG_INF; bx[j] = NB; }
        for (int t = 0; t < 384; t++) {
            float s = sv[t]; int n = si[t];
            if (n >= NB) continue;
            if (better(s, n, bv[7], bx[7])) {
                int j = 7;
                while (j > 0 && better(s, n, bv[j - 1], bx[j - 1])) {
                    bv[j] = bv[j - 1]; bx[j] = bx[j - 1]; j--;
                }
                bv[j] = s; bx[j] = n;
            }
        }
#pragma unroll
        for (int j = 0; j < 8; j++) cand[j] = bx[j];
    }
    __syncthreads();

    // phase 3: exact fp32 cosine sims for the 8 candidates
    __shared__ float cval[8];
    const int warp = tid >> 5, lane = tid & 31;
    const float* pr = P + (size_t)r * NF;
    for (int c = warp; c < 8; c += 4) {
        int n = cand[c];
        if (n >= NB) { if (lane == 0) cval[c] = NEG_INF; continue; }
        const float* pc = P + (size_t)n * NF;
        float s = 0.f;
#pragma unroll 4
        for (int f = lane; f < NF; f += 32) s += pr[f] * pc[f];
#pragma unroll
        for (int o = 16; o; o >>= 1) s += __shfl_xor_sync(0xffffffffu, s, o);
        if (lane == 0) cval[c] = s / fmaxf(ni * nrm[n], 1e-8f);
    }
    __syncthreads();

    // phase 4: exact top-3 of the 8 + softmax
    __shared__ float w[3];
    __shared__ int   bi[3];
    if (tid == 0) {
        float b0 = NEG_INF, b1 = NEG_INF, b2 = NEG_INF;
        int   j0 = NB, j1 = NB, j2 = NB;
        for (int t = 0; t < 8; t++) {
            float s = cval[t]; int n = cand[t];
            if (n >= NB) continue;
            if (better(s, n, b0, j0)) { b2 = b1; j2 = j1; b1 = b0; j1 = j0; b0 = s; j0 = n; }
            else if (better(s, n, b1, j1)) { b2 = b1; j2 = j1; b1 = s; j1 = n; }
            else if (better(s, n, b2, j2)) { b2 = s; j2 = n; }
        }
        float e0 = 1.0f, e1 = expf(b1 - b0), e2 = expf(b2 - b0);
        float inv = 1.0f / (e0 + e1 + e2);
        w[0] = e0 * inv; w[1] = e1 * inv; w[2] = e2 * inv;
        bi[0] = j0; bi[1] = j1; bi[2] = j2;
    }
    __syncthreads();

    // phase 5: weighted fill + refresh fp16 hi
    const float* f0 = P + (size_t)bi[0] * NF;
    const float* f1 = P + (size_t)bi[1] * NF;
    const float* f2 = P + (size_t)bi[2] * NF;
    const float w0 = w[0], w1 = w[1], w2 = w[2];
    for (int f = tid * 2; f < NF; f += 256) {
        float a0 = w0 * f0[f]     + w1 * f1[f]     + w2 * f2[f];
        float a1 = w0 * f0[f + 1] + w1 * f1[f + 1] + w2 * f2[f + 1];
        size_t off = (size_t)r * NF + f;
        *(float2*)(P + off) = make_float2(a0, a1);
        *(__half2*)(Ph + off) = __halves2half2(__float2half_rn(a0), __float2half_rn(a1));
    }
}

// ---------------- fused concat GEMM + ReLU + W2-dot partials -----------------
__global__ void __launch_bounds__(256) k_h_mma(const float* __restrict__ b1,
                                               const float* __restrict__ W2) {
    const int m0 = blockIdx.y * 128, n0 = blockIdx.x * 64;
    extern __shared__ __align__(16) char sm[];
    const uint32_t sb = s2u(sm);
    const int tid = threadIdx.x, lane = tid & 31, warp = tid >> 5;
    const int wm = warp & 3, wn = warp >> 2;

    auto load = [&](int it, int st) {
        const int mod = it >> 3, kk = (it & 7) << 6;
        const hf* Ah = g_ph[mod];
        uint32_t b = sb + st * STGH;
#pragma unroll
        for (int i = 0; i < 4; i++) {
            int c = tid + i * 256, m = c >> 3, k8 = c & 7;
            cpa(b + swz(m, k8), Ah + (size_t)(m0 + m) * NF + kk + k8 * 8);
        }
#pragma unroll
        for (int i = 0; i < 2; i++) {
            int c = tid + i * 256, k = c >> 3, n8 = c & 7;
            size_t off = (size_t)(mod * NF + kk + k) * NF + n0 + n8 * 8;
            cpa(b + HOFF_B + swz(k, n8), g_w1h + off);
        }
        cpcommit();
    };

    float acc[2][4][4] = {};
    load(0, 0);
    const int ITERS = 24;  // 3 modalities x 8 BK-tiles
    for (int it = 0; it < ITERS; it++) {
        if (it + 1 < ITERS) { load(it + 1, (it + 1) & 1); cpwait1(); } else cpwait0();
        __syncthreads();
        stage1_nn(sb + (it & 1) * STGH, wm, wn, lane, acc);
        __syncthreads();
    }

    const int g = lane >> 2, tg = lane & 3;
    float op[2][2] = {};
#pragma unroll
    for (int mt = 0; mt < 2; mt++)
#pragma unroll
        for (int nt = 0; nt < 4; nt++) {
            int col = n0 + wn * 32 + nt * 8 + tg * 2;
            float bz0 = b1[col], bz1 = b1[col + 1];
            float w20 = W2[col], w21 = W2[col + 1];
#pragma unroll
            for (int hh = 0; hh < 2; hh++) {
                float v0 = fmaxf(acc[mt][nt][hh * 2 + 0] + bz0, 0.f);
                float v1 = fmaxf(acc[mt][nt][hh * 2 + 1] + bz1, 0.f);
                op[mt][hh] += v0 * w20 + v1 * w21;
            }
        }
#pragma unroll
    for (int mt = 0; mt < 2; mt++)
#pragma unroll
        for (int hh = 0; hh < 2; hh++) {
            float s = op[mt][hh];
            s += __shfl_xor_sync(0xffffffffu, s, 1);
            s += __shfl_xor_sync(0xffffffffu, s, 2);
            if (tg == 0) {
                int row = m0 + wm * 32 + mt * 16 + g + hh * 8;
                g_outp[(size_t)row * 16 + blockIdx.x * 2 + wn] = s;
            }
        }
}

// ---------------- out[m] = sum of 16 partials + b2 ---------------------------
__global__ void __launch_bounds__(256) k_out2(const float* __restrict__ b2,
                                              float* __restrict__ out) {
    const int m = blockIdx.x * 256 + threadIdx.x;
    if (m >= NB) return;
    const float* p = g_outp + (size_t)m * 16;
    float s = 0.f;
#pragma unroll
    for (int j = 0; j < 16; j++) s += p[j];
    out[m] = s + b2[0];
}

// ---------------- launcher ----------------------------------------------------
extern "C" void kernel_launch(void* const* d_in, const int* in_sizes, int n_in,
                              void* d_out, int out_size) {
    const float* lang = (const float*)d_in[0];
    const float* vid  = (const float*)d_in[1];
    const float* aud  = (const float*)d_in[2];
    const int*   mi   = (const int*)d_in[3];
    const float* Wl   = (const float*)d_in[4];
    const float* bl   = (const float*)d_in[5];
    const float* Wv   = (const float*)d_in[6];
    const float* bv   = (const float*)d_in[7];
    const float* Wa   = (const float*)d_in[8];
    const float* ba   = (const float*)d_in[9];
    const float* W1   = (const float*)d_in[10];
    const float* b1   = (const float*)d_in[11];
    const float* W2   = (const float*)d_in[12];
    const float* b2   = (const float*)d_in[13];
    float* out = (float*)d_out;

    cudaFuncSetAttribute(k_proj_mma, cudaFuncAttributeMaxDynamicSharedMemorySize, DSM);
    cudaFuncSetAttribute(k_sim_mma,  cudaFuncAttributeMaxDynamicSharedMemorySize, SDSM);
    cudaFuncSetAttribute(k_h_mma,    cudaFuncAttributeMaxDynamicSharedMemorySize, DSMH);

    // one combined split launch (also resets counters); X segments are largest
    k_splitall<<<dim3((NB * ND / 4) / 256, 7), 256>>>(lang, vid, aud, Wl, Wv, Wa, W1);
    k_build<<<NB / 256, 256>>>(mi);

    k_proj_mma<<<dim3(NF / 64, NB / 128, 3), 256, DSM>>>(bl, bv, ba);
    k_norm2<<<dim3(NB / 256, 3), 256>>>();

    k_sim_mma<<<dim3(NB / 64, NB / 128, 3), 256, SDSM>>>();
    k_topk<<<dim3(NB, 1, 3), 128>>>();

    k_h_mma<<<dim3(NF / 64, NB / 128), 256, DSMH>>>(b1, W2);
    k_out2<<<NB / 256, 256>>>(b2, out);
}